// round 8
// baseline (speedup 1.0000x reference)
#include <cuda_runtime.h>
#include <cstdint>

#define NVOX (64*64*64)      // 262144 voxels
#define NQ   (NVOX/4)        // 65536 float4 per (b,k) slab
#define BKN  28              // 4 batches * 7 moving parts
#define NBLK 128             // 4 batches * 32 segments; 1 block/SM, all co-resident
#define SEGS 32
#define SEG_F4 2048          // float4 per slab-segment (32 KB)
#define THREADS 1024         // 32 warps/SM

// ---- dynamic smem layout (float offsets) ----
#define OFF_SLAB  0                    // 7 * 8192 floats = 224 KB
#define OFF_AX    57344
#define OFF_AY    57408
#define OFF_AZ    57472
#define OFF_WPART 57536                // 32 warps * 4 comps (reused per k)
#define OFF_P7    57664                // 28 floats: this block's (k,comp) partials
#define OFF_CF    57692                // 84 floats (this batch's coefficients)
#define OFF_MBAR  57776                // 7 mbarriers (uint64), byte 231104, 8-aligned
#define SMEM_BYTES 231160              // <= 232448 (227 KB per-block max)

// Scratch + barrier state (no allocations allowed)
__device__ float    g_partial[NBLK * BKN];   // [block][k*4+comp]
__device__ float    g_coef[BKN * 12];        // [0..8]=M=R-I, [9..11]=d
__device__ unsigned g_count = 0;             // self-resets every launch
__device__ unsigned g_gen   = 0;             // monotonically increasing

// ---------------- PTX helpers ----------------
__device__ __forceinline__ uint32_t smem_u32(const void* p) {
    uint32_t a;
    asm("{ .reg .u64 t; cvta.to.shared.u64 t, %1; cvt.u32.u64 %0, t; }"
        : "=r"(a) : "l"(p));
    return a;
}
__device__ __forceinline__ void mbar_init(uint32_t mbar, uint32_t count) {
    asm volatile("mbarrier.init.shared.b64 [%0], %1;" :: "r"(mbar), "r"(count) : "memory");
}
__device__ __forceinline__ void mbar_expect_tx(uint32_t mbar, uint32_t bytes) {
    asm volatile("mbarrier.arrive.expect_tx.shared.b64 _, [%0], %1;"
                 :: "r"(mbar), "r"(bytes) : "memory");
}
__device__ __forceinline__ void mbar_wait0(uint32_t mbar) {
    asm volatile(
        "{\n\t.reg .pred P;\n\t"
        "W_%=:\n\t"
        "mbarrier.try_wait.parity.shared::cta.b64 P, [%0], 0;\n\t"
        "@!P bra W_%=;\n\t}"
        :: "r"(mbar) : "memory");
}
__device__ __forceinline__ void bulk_copy(uint32_t dst_smem, const void* src_gmem,
                                          uint32_t bytes, uint32_t mbar) {
    asm volatile(
        "cp.async.bulk.shared::cta.global.mbarrier::complete_tx::bytes [%0], [%1], %2, [%3];"
        :: "r"(dst_smem), "l"(src_gmem), "r"(bytes), "r"(mbar) : "memory");
}
__device__ __forceinline__ void fence_async_shared() {
    asm volatile("fence.proxy.async.shared::cta;" ::: "memory");
}

// ---------------------------------------------------------------------------
// Single-pass fused kernel, 1024 threads (32 warps/SM).
//   Phase 1: TMA-copy 7x32KB slabs in, reduce (sum m, m*gx, m*gy, m*gz) per k.
//   Barrier: last block folds 128x28 partials -> 28 coefficient sets
//            M = R - I, d = p + t - R p.
//   Phase 2: motion[b,c,v] = sum_k mask[b,k,v]*(M_bk[c,:].g_v + d_bk[c])
//            straight out of smem; 12 MB streamed out.
// ---------------------------------------------------------------------------
__global__ void __launch_bounds__(THREADS, 1)
fused_k(const float* __restrict__ mask, const float* __restrict__ grids,
        const float* __restrict__ trans_vec, const float* __restrict__ rot_mat,
        float* __restrict__ out)
{
    extern __shared__ __align__(16) float sm[];
    const int tid = threadIdx.x;
    const int bid = blockIdx.x;
    const int b   = bid >> 5;            // batch
    const int seg = bid & 31;            // segment within batch

    float4* slab4 = (float4*)(sm + OFF_SLAB);
    float* ax = sm + OFF_AX; float* ay = sm + OFF_AY; float* az = sm + OFF_AZ;
    float* wpart = sm + OFF_WPART;
    float* p7 = sm + OFF_P7;
    float* cf = sm + OFF_CF;
    unsigned long long* mbar = (unsigned long long*)(sm + OFF_MBAR);

    __shared__ unsigned sh_gen;
    __shared__ bool     is_last;

    if (tid == 0) sh_gen = *(volatile unsigned*)&g_gen;    // entry generation
    if (tid < 7) mbar_init(smem_u32(&mbar[tid]), 1);
    if (tid < 64) {
        ax[tid] = grids[tid << 12];                 // separable meshgrid axes
        ay[tid] = grids[NVOX + (tid << 6)];
        az[tid] = grids[2 * NVOX + tid];
    }
    __syncthreads();                                // mbar init + gen visible
    const unsigned gen0 = sh_gen;

    // ---------------- issue all 7 bulk copies up front ----------------
    const float* srcb = mask + ((size_t)b * 8) * NVOX + (size_t)seg * (SEG_F4 * 4);
    if (tid == 0) {
        fence_async_shared();
#pragma unroll
        for (int k = 0; k < 7; ++k) {
            const uint32_t mb = smem_u32(&mbar[k]);
            mbar_expect_tx(mb, SEG_F4 * 16);
            bulk_copy(smem_u32(sm + OFF_SLAB) + k * SEG_F4 * 16,
                      srcb + (size_t)k * NVOX, SEG_F4 * 16, mb);
        }
    }

    // ---------------- Phase 1: reduce each slab as it lands ----------------
    const int w = tid >> 5, l = tid & 31;
    const int vseg = seg * (SEG_F4 * 4);            // first voxel of this segment
#pragma unroll
    for (int k = 0; k < 7; ++k) {
        mbar_wait0(smem_u32(&mbar[k]));
        float s0 = 0.f, sx = 0.f, sy = 0.f, sz = 0.f;
#pragma unroll
        for (int it = 0; it < SEG_F4 / THREADS; ++it) {   // 2 f4 per thread
            const int idx = it * THREADS + tid;
            const float4 m = slab4[k * SEG_F4 + idx];
            const int v  = vseg + (idx << 2);
            const int i  = v >> 12;
            const int j  = (v >> 6) & 63;
            const int kk = v & 63;
            const float ms = (m.x + m.y) + (m.z + m.w);
            s0 += ms;
            sx = fmaf(ax[i], ms, sx);
            sy = fmaf(ay[j], ms, sy);
            sz = fmaf(az[kk],     m.x,
                 fmaf(az[kk + 1], m.y,
                 fmaf(az[kk + 2], m.z,
                 fmaf(az[kk + 3], m.w, sz))));
        }
#pragma unroll
        for (int off = 16; off; off >>= 1) {
            s0 += __shfl_down_sync(0xFFFFFFFFu, s0, off);
            sx += __shfl_down_sync(0xFFFFFFFFu, sx, off);
            sy += __shfl_down_sync(0xFFFFFFFFu, sy, off);
            sz += __shfl_down_sync(0xFFFFFFFFu, sz, off);
        }
        if (l == 0) {
            float* wp = wpart + w * 4;
            wp[0] = s0; wp[1] = sx; wp[2] = sy; wp[3] = sz;
        }
        __syncthreads();                              // wpart filled
        if (tid < 4) {                                // fold 32 warps -> (k,comp)
            float s = 0.f;
#pragma unroll
            for (int ww = 0; ww < 32; ++ww)
                s += wpart[ww * 4 + tid];
            p7[k * 4 + tid] = s;
        }
        __syncthreads();                              // wpart reusable
    }

    // publish this block's 28 partials
    if (tid < BKN) {
        g_partial[bid * BKN + tid] = p7[tid];
        __threadfence();                              // publish before arrival
    }
    __syncthreads();

    // ---------------- grid barrier (all 128 blocks co-resident) ----------------
    if (tid == 0) {
        const unsigned arrived = atomicAdd(&g_count, 1u);
        is_last = (arrived == NBLK - 1);
        if (is_last) g_count = 0;                    // reset for next replay
    }
    __syncthreads();

    if (is_last) {
        if (tid < BKN * 4) {                         // 112: (bk, comp)
            const int bk = tid >> 2, comp = tid & 3;
            const int fb = bk / 7, fk = bk % 7;
            float s = 0.f;
#pragma unroll
            for (int c = 0; c < SEGS; ++c)
                s += __ldcg(&g_partial[(fb * SEGS + c) * BKN + fk * 4 + comp]);
            wpart[bk * 4 + comp] = s;                // reuse wpart (128 floats)
        }
        __syncthreads();
        if (tid < BKN) {
            const float inv = 1.f / wpart[tid * 4 + 0];
            const float pv[3] = { wpart[tid * 4 + 1] * inv,
                                  wpart[tid * 4 + 2] * inv,
                                  wpart[tid * 4 + 3] * inv };
            const float* R = rot_mat   + tid * 9;
            const float* t = trans_vec + tid * 3;
            float* c = g_coef + tid * 12;
#pragma unroll
            for (int r = 0; r < 3; ++r) {
                const float Rp = R[r * 3] * pv[0] + R[r * 3 + 1] * pv[1] + R[r * 3 + 2] * pv[2];
                c[r * 3 + 0] = R[r * 3 + 0] - (r == 0 ? 1.f : 0.f);
                c[r * 3 + 1] = R[r * 3 + 1] - (r == 1 ? 1.f : 0.f);
                c[r * 3 + 2] = R[r * 3 + 2] - (r == 2 ? 1.f : 0.f);
                c[9 + r]     = pv[r] + t[r] - Rp;
            }
            __threadfence();                         // publish coefs
        }
        __syncthreads();
        if (tid == 0) atomicAdd(&g_gen, 1u);         // release
    } else {
        if (tid == 0) {
            while (*(volatile unsigned*)&g_gen == gen0) { }
            __threadfence();                         // acquire
        }
        __syncthreads();
    }

    // load this batch's 84 coefficients
    if (tid < 84) cf[tid] = __ldcg(&g_coef[b * 84 + tid]);
    __syncthreads();

    // ---------------- Phase 2: apply from smem, stream out ----------------
    float4* o4 = (float4*)out;
#pragma unroll
    for (int it = 0; it < SEG_F4 / THREADS; ++it) {  // 2 f4 per thread
        const int idx = it * THREADS + tid;
        const int v  = vseg + (idx << 2);
        const int i  = v >> 12;
        const int j  = (v >> 6) & 63;
        const int kk = v & 63;
        const float gx = ax[i], gy = ay[j];
        const float gz[4] = { az[kk], az[kk + 1], az[kk + 2], az[kk + 3] };

        float mot[3][4] = {};
#pragma unroll
        for (int k = 0; k < 7; ++k) {
            const float4 m = slab4[k * SEG_F4 + idx];
            const float mvv[4] = { m.x, m.y, m.z, m.w };
            const float* c = cf + k * 12;
#pragma unroll
            for (int cc = 0; cc < 3; ++cc) {
                const float m2   = c[cc * 3 + 2];
                const float base = fmaf(c[cc * 3], gx, fmaf(c[cc * 3 + 1], gy, c[9 + cc]));
#pragma unroll
                for (int t = 0; t < 4; ++t)
                    mot[cc][t] = fmaf(mvv[t], fmaf(m2, gz[t], base), mot[cc][t]);
            }
        }
        const int of4 = seg * SEG_F4 + idx;
#pragma unroll
        for (int cc = 0; cc < 3; ++cc) {
            float4 o = { mot[cc][0], mot[cc][1], mot[cc][2], mot[cc][3] };
            __stcs(&o4[((size_t)b * 3 + cc) * NQ + of4], o);
        }
    }
}

// ---------------------------------------------------------------------------
extern "C" void kernel_launch(void* const* d_in, const int* in_sizes, int n_in,
                              void* d_out, int out_size)
{
    const float* mask = nullptr;
    const float* tv   = nullptr;
    const float* rm   = nullptr;
    const float* gr   = nullptr;
    for (int i = 0; i < n_in; ++i) {
        switch (in_sizes[i]) {
            case 8388608: mask = (const float*)d_in[i]; break;   // (4,8,64,64,64)
            case 84:      tv   = (const float*)d_in[i]; break;   // (4,7,3)
            case 252:     rm   = (const float*)d_in[i]; break;   // (4,7,3,3)
            case 786432:  gr   = (const float*)d_in[i]; break;   // (3,64,64,64)
        }
    }
    cudaFuncSetAttribute(fused_k, cudaFuncAttributeMaxDynamicSharedMemorySize, SMEM_BYTES);
    fused_k<<<NBLK, THREADS, SMEM_BYTES>>>(mask, gr, tv, rm, (float*)d_out);
}

// round 9
// speedup vs baseline: 1.6037x; 1.6037x over previous
#include <cuda_runtime.h>
#include <cstdint>

#define NVOX (64*64*64)        // 262144 voxels
#define NQ   (NVOX/4)          // 65536 float4 per (b,k) slab
#define BKN 28                 // 4 batches * 7 moving parts
#define CHUNKS 32              // partial-reduction chunks per (b,k)
#define NBLOCKS (BKN * CHUNKS) // 896 reduce blocks
#define RED_THREADS 256
#define APPLY_THREADS 256

// Scratch (no allocations allowed)
__device__ float    g_partial[NBLOCKS * 4];
__device__ float    g_coef[BKN * 12];     // [0..8]=M=R-I row-major, [9..11]=d
__device__ unsigned g_count = 0;          // self-resets every launch

// ---------------- cp.async helpers (per-thread 16B copies, no register hold) ----
__device__ __forceinline__ uint32_t smem_u32(const void* p) {
    uint32_t a;
    asm("{ .reg .u64 t; cvta.to.shared.u64 t, %1; cvt.u32.u64 %0, t; }"
        : "=r"(a) : "l"(p));
    return a;
}
__device__ __forceinline__ void cp_async16(uint32_t dst_smem, const void* src) {
    asm volatile("cp.async.cg.shared.global [%0], [%1], 16;"
                 :: "r"(dst_smem), "l"(src) : "memory");
}
__device__ __forceinline__ void cp_async_commit_wait() {
    asm volatile("cp.async.commit_group;" ::: "memory");
    asm volatile("cp.async.wait_group 0;" ::: "memory");
}

// ---------------------------------------------------------------------------
// Pass 1: per-(b,k) weighted sums (sum m, sum m*gx, sum m*gy, sum m*gz).
// Each thread issues 8 x 16B cp.async (all in flight, zero register cost),
// waits, reduces from its own smem slots. LAST block folds partials ->
// coefficients: M = R - I, d = p + t - R p.
// ---------------------------------------------------------------------------
__global__ void __launch_bounds__(RED_THREADS, 6)
reduce_k(const float* __restrict__ mask, const float* __restrict__ grids,
         const float* __restrict__ trans_vec, const float* __restrict__ rot_mat)
{
    const int bk    = blockIdx.x >> 5;     // / CHUNKS
    const int chunk = blockIdx.x & 31;     // % CHUNKS
    const int b = bk / 7, k = bk % 7;
    const int tid = threadIdx.x;

    __shared__ __align__(16) float4 buf[2048];      // 32 KB chunk
    __shared__ float ax[64], ay[64], az[64];
    __shared__ float red[8][4];
    __shared__ float fold[BKN][4];
    __shared__ bool  is_last;

    const float4* m4 = (const float4*)(mask + ((size_t)(b * 8 + k)) * NVOX)
                       + (size_t)chunk * 2048;

    // ---- 8 async copies per thread, all in flight immediately ----
#pragma unroll
    for (int t = 0; t < 8; ++t)
        cp_async16(smem_u32(&buf[t * RED_THREADS + tid]), &m4[t * RED_THREADS + tid]);
    asm volatile("cp.async.commit_group;" ::: "memory");

    if (tid < 64) {
        ax[tid] = grids[tid << 12];                 // gx[i,0,0]
        ay[tid] = grids[NVOX + (tid << 6)];         // gy[0,j,0]
        az[tid] = grids[2 * NVOX + tid];            // gz[0,0,k]
    }
    __syncthreads();                                 // axes ready

    asm volatile("cp.async.wait_group 0;" ::: "memory");  // own 16B slots ready

    const int vbase = chunk * (NVOX / CHUNKS);
    float s0 = 0.f, sx = 0.f, sy = 0.f, sz = 0.f;
#pragma unroll
    for (int t = 0; t < 8; ++t) {
        const int idx4 = t * RED_THREADS + tid;
        const float4 m = buf[idx4];                 // conflict-free LDS.128
        const int v  = vbase + (idx4 << 2);
        const int i  = v >> 12;
        const int j  = (v >> 6) & 63;
        const int kk = v & 63;
        const float ms = (m.x + m.y) + (m.z + m.w);
        s0 += ms;
        sx = fmaf(ax[i], ms, sx);
        sy = fmaf(ay[j], ms, sy);
        sz = fmaf(az[kk],     m.x,
             fmaf(az[kk + 1], m.y,
             fmaf(az[kk + 2], m.z,
             fmaf(az[kk + 3], m.w, sz))));
    }

    // warp tree reduce (deterministic)
#pragma unroll
    for (int off = 16; off; off >>= 1) {
        s0 += __shfl_down_sync(0xFFFFFFFFu, s0, off);
        sx += __shfl_down_sync(0xFFFFFFFFu, sx, off);
        sy += __shfl_down_sync(0xFFFFFFFFu, sy, off);
        sz += __shfl_down_sync(0xFFFFFFFFu, sz, off);
    }
    const int w = tid >> 5, l = tid & 31;
    if (l == 0) { red[w][0] = s0; red[w][1] = sx; red[w][2] = sy; red[w][3] = sz; }
    __syncthreads();
    if (tid == 0) {
        float r0 = 0.f, r1 = 0.f, r2 = 0.f, r3 = 0.f;
#pragma unroll
        for (int i = 0; i < 8; ++i) {
            r0 += red[i][0]; r1 += red[i][1]; r2 += red[i][2]; r3 += red[i][3];
        }
        float* p = g_partial + blockIdx.x * 4;
        p[0] = r0; p[1] = r1; p[2] = r2; p[3] = r3;
        __threadfence();                                // publish partial
        const unsigned arrived = atomicAdd(&g_count, 1u);
        is_last = (arrived == NBLOCKS - 1);
        if (is_last) g_count = 0;                       // reset for next replay
    }
    __syncthreads();
    if (!is_last) return;

    // -------- last block: fold partials -> coefficients (L2-hot) --------
    if (tid < BKN * 4) {                 // 112 threads: one (bk, component) each
        const int fbk  = tid >> 2;
        const int comp = tid & 3;
        const float* p = g_partial + (fbk * CHUNKS) * 4 + comp;
        float s = 0.f;
#pragma unroll
        for (int c = 0; c < CHUNKS; ++c)
            s += __ldcg(p + c * 4);
        fold[fbk][comp] = s;
    }
    __syncthreads();
    if (tid < BKN) {
        const float inv = 1.f / fold[tid][0];
        const float pv[3] = { fold[tid][1] * inv, fold[tid][2] * inv, fold[tid][3] * inv };
        const float* R = rot_mat   + tid * 9;
        const float* t = trans_vec + tid * 3;
        float* c = g_coef + tid * 12;
#pragma unroll
        for (int r = 0; r < 3; ++r) {
            const float Rp = R[r * 3] * pv[0] + R[r * 3 + 1] * pv[1] + R[r * 3 + 2] * pv[2];
            c[r * 3 + 0] = R[r * 3 + 0] - (r == 0 ? 1.f : 0.f);
            c[r * 3 + 1] = R[r * 3 + 1] - (r == 1 ? 1.f : 0.f);
            c[r * 3 + 2] = R[r * 3 + 2] - (r == 2 ? 1.f : 0.f);
            c[9 + r]     = pv[r] + t[r] - Rp;
        }
    }
}

// ---------------------------------------------------------------------------
// Pass 2: motion[b,c,v] = sum_{k<7} mask[b,k,v] * (M_bk[c,:].g_v + d_bk[c]).
// 7 x 16B cp.async per thread (all in flight), block-constant gx, coefficients
// in smem. Mask is L2-hot from pass 1.
// ---------------------------------------------------------------------------
__global__ void __launch_bounds__(APPLY_THREADS, 6)
apply_k(const float* __restrict__ mask, const float* __restrict__ grids,
        float* __restrict__ out)
{
    const int blocksPerB = NQ / APPLY_THREADS;   // 256
    const int b   = blockIdx.x / blocksPerB;
    const int blk = blockIdx.x % blocksPerB;
    const int tid = threadIdx.x;

    __shared__ __align__(16) float4 sbuf[7 * 256];   // 28 KB: 7 mask slices
    __shared__ float cf[84];
    __shared__ float ay[64], az[64];

    const int idx4 = blk * APPLY_THREADS + tid;
    const float4* mb = (const float4*)mask + ((size_t)b * 8) * NQ + idx4;

    // ---- 7 async copies per thread, all in flight immediately ----
#pragma unroll
    for (int k = 0; k < 7; ++k)
        cp_async16(smem_u32(&sbuf[k * 256 + tid]), &mb[(size_t)k * NQ]);
    asm volatile("cp.async.commit_group;" ::: "memory");

    if (tid < 84) cf[tid] = g_coef[b * 84 + tid];
    if (tid < 64) {
        ay[tid] = grids[NVOX + (tid << 6)];
        az[tid] = grids[2 * NVOX + tid];
    }
    const float gx = grids[(size_t)(blk >> 2) << 12];   // block-constant x-plane
    __syncthreads();                                    // cf + axes ready

    asm volatile("cp.async.wait_group 0;" ::: "memory");  // own 16B slots ready

    const int v  = idx4 << 2;
    const int j  = (v >> 6) & 63;
    const int kk = v & 63;
    const float gy = ay[j];
    const float gz[4] = { az[kk], az[kk + 1], az[kk + 2], az[kk + 3] };

    float mot[3][4] = {};
#pragma unroll
    for (int k = 0; k < 7; ++k) {
        const float4 m = sbuf[k * 256 + tid];
        const float mvv[4] = { m.x, m.y, m.z, m.w };
        const float* c = cf + k * 12;
#pragma unroll
        for (int cc = 0; cc < 3; ++cc) {
            const float m2   = c[cc * 3 + 2];
            const float base = fmaf(c[cc * 3], gx, fmaf(c[cc * 3 + 1], gy, c[9 + cc]));
#pragma unroll
            for (int t = 0; t < 4; ++t)
                mot[cc][t] = fmaf(mvv[t], fmaf(m2, gz[t], base), mot[cc][t]);
        }
    }

    float4* o4 = (float4*)out;
#pragma unroll
    for (int cc = 0; cc < 3; ++cc) {
        float4 o = { mot[cc][0], mot[cc][1], mot[cc][2], mot[cc][3] };
        o4[((size_t)b * 3 + cc) * NQ + idx4] = o;
    }
}

// ---------------------------------------------------------------------------
extern "C" void kernel_launch(void* const* d_in, const int* in_sizes, int n_in,
                              void* d_out, int out_size)
{
    const float* mask = nullptr;
    const float* tv   = nullptr;
    const float* rm   = nullptr;
    const float* gr   = nullptr;
    for (int i = 0; i < n_in; ++i) {
        switch (in_sizes[i]) {
            case 8388608: mask = (const float*)d_in[i]; break;   // (4,8,64,64,64)
            case 84:      tv   = (const float*)d_in[i]; break;   // (4,7,3)
            case 252:     rm   = (const float*)d_in[i]; break;   // (4,7,3,3)
            case 786432:  gr   = (const float*)d_in[i]; break;   // (3,64,64,64)
        }
    }
    reduce_k<<<NBLOCKS, RED_THREADS>>>(mask, gr, tv, rm);
    apply_k<<<4 * (NQ / APPLY_THREADS), APPLY_THREADS>>>(mask, gr, (float*)d_out);
}

// round 10
// speedup vs baseline: 1.6584x; 1.0342x over previous
#include <cuda_runtime.h>
#include <cstdint>

#define NVOX (64*64*64)        // 262144 voxels
#define NQ   (NVOX/4)          // 65536 float4 per (b,k) slab
#define BKN 28                 // 4 batches * 7 moving parts
#define CHUNKS 32              // partial-reduction chunks per (b,k)
#define NBLOCKS (BKN * CHUNKS) // 896 reduce blocks
#define RED_THREADS 256
#define APPLY_THREADS 256

// Scratch (no allocations allowed)
__device__ float    g_partial[NBLOCKS * 4];
__device__ float    g_coef[BKN * 12];     // [0..8]=M=R-I row-major, [9..11]=d
__device__ unsigned g_count = 0;          // self-resets every launch

// ---------------- helpers ----------------
__device__ __forceinline__ uint32_t smem_u32(const void* p) {
    uint32_t a;
    asm("{ .reg .u64 t; cvta.to.shared.u64 t, %1; cvt.u32.u64 %0, t; }"
        : "=r"(a) : "l"(p));
    return a;
}
__device__ __forceinline__ void cp_async16(uint32_t dst_smem, const void* src) {
    asm volatile("cp.async.cg.shared.global [%0], [%1], 16;"
                 :: "r"(dst_smem), "l"(src) : "memory");
}
__device__ __forceinline__ void pdl_trigger() {          // allow dependent grid launch
    asm volatile("griddepcontrol.launch_dependents;");
}
__device__ __forceinline__ void pdl_wait() {             // wait for primary grid done
    asm volatile("griddepcontrol.wait;" ::: "memory");
}

// ---------------------------------------------------------------------------
// Pass 1 (primary): per-(b,k) weighted sums (sum m, sum m*gx, m*gy, m*gz).
// Each thread issues 8 x 16B cp.async, then the block signals PDL so apply_k
// can start prefetching concurrently. LAST block folds partials ->
// coefficients: M = R - I, d = p + t - R p.
// ---------------------------------------------------------------------------
__global__ void __launch_bounds__(RED_THREADS, 6)
reduce_k(const float* __restrict__ mask, const float* __restrict__ grids,
         const float* __restrict__ trans_vec, const float* __restrict__ rot_mat)
{
    const int bk    = blockIdx.x >> 5;     // / CHUNKS
    const int chunk = blockIdx.x & 31;     // % CHUNKS
    const int b = bk / 7, k = bk % 7;
    const int tid = threadIdx.x;

    __shared__ __align__(16) float4 buf[2048];      // 32 KB chunk
    __shared__ float ax[64], ay[64], az[64];
    __shared__ float red[8][4];
    __shared__ float fold[BKN][4];
    __shared__ bool  is_last;

    const float4* m4 = (const float4*)(mask + ((size_t)(b * 8 + k)) * NVOX)
                       + (size_t)chunk * 2048;

    // ---- 8 async copies per thread, all in flight immediately ----
#pragma unroll
    for (int t = 0; t < 8; ++t)
        cp_async16(smem_u32(&buf[t * RED_THREADS + tid]), &m4[t * RED_THREADS + tid]);
    asm volatile("cp.async.commit_group;" ::: "memory");

    pdl_trigger();                                   // let apply_k start prefetch

    if (tid < 64) {
        ax[tid] = grids[tid << 12];                 // gx[i,0,0]
        ay[tid] = grids[NVOX + (tid << 6)];         // gy[0,j,0]
        az[tid] = grids[2 * NVOX + tid];            // gz[0,0,k]
    }
    __syncthreads();                                 // axes ready

    asm volatile("cp.async.wait_group 0;" ::: "memory");  // own 16B slots ready

    const int vbase = chunk * (NVOX / CHUNKS);
    float s0 = 0.f, sx = 0.f, sy = 0.f, sz = 0.f;
#pragma unroll
    for (int t = 0; t < 8; ++t) {
        const int idx4 = t * RED_THREADS + tid;
        const float4 m = buf[idx4];                 // conflict-free LDS.128
        const int v  = vbase + (idx4 << 2);
        const int i  = v >> 12;
        const int j  = (v >> 6) & 63;
        const int kk = v & 63;
        const float ms = (m.x + m.y) + (m.z + m.w);
        s0 += ms;
        sx = fmaf(ax[i], ms, sx);
        sy = fmaf(ay[j], ms, sy);
        sz = fmaf(az[kk],     m.x,
             fmaf(az[kk + 1], m.y,
             fmaf(az[kk + 2], m.z,
             fmaf(az[kk + 3], m.w, sz))));
    }

    // warp tree reduce (deterministic)
#pragma unroll
    for (int off = 16; off; off >>= 1) {
        s0 += __shfl_down_sync(0xFFFFFFFFu, s0, off);
        sx += __shfl_down_sync(0xFFFFFFFFu, sx, off);
        sy += __shfl_down_sync(0xFFFFFFFFu, sy, off);
        sz += __shfl_down_sync(0xFFFFFFFFu, sz, off);
    }
    const int w = tid >> 5, l = tid & 31;
    if (l == 0) { red[w][0] = s0; red[w][1] = sx; red[w][2] = sy; red[w][3] = sz; }
    __syncthreads();
    if (tid == 0) {
        float r0 = 0.f, r1 = 0.f, r2 = 0.f, r3 = 0.f;
#pragma unroll
        for (int i = 0; i < 8; ++i) {
            r0 += red[i][0]; r1 += red[i][1]; r2 += red[i][2]; r3 += red[i][3];
        }
        float* p = g_partial + blockIdx.x * 4;
        p[0] = r0; p[1] = r1; p[2] = r2; p[3] = r3;
        __threadfence();                                // publish partial
        const unsigned arrived = atomicAdd(&g_count, 1u);
        is_last = (arrived == NBLOCKS - 1);
        if (is_last) g_count = 0;                       // reset for next replay
    }
    __syncthreads();
    if (!is_last) return;

    // -------- last block: fold partials -> coefficients (L2-hot) --------
    if (tid < BKN * 4) {                 // 112 threads: one (bk, component) each
        const int fbk  = tid >> 2;
        const int comp = tid & 3;
        const float* p = g_partial + (fbk * CHUNKS) * 4 + comp;
        float s = 0.f;
#pragma unroll
        for (int c = 0; c < CHUNKS; ++c)
            s += __ldcg(p + c * 4);
        fold[fbk][comp] = s;
    }
    __syncthreads();
    if (tid < BKN) {
        const float inv = 1.f / fold[tid][0];
        const float pv[3] = { fold[tid][1] * inv, fold[tid][2] * inv, fold[tid][3] * inv };
        const float* R = rot_mat   + tid * 9;
        const float* t = trans_vec + tid * 3;
        float* c = g_coef + tid * 12;
#pragma unroll
        for (int r = 0; r < 3; ++r) {
            const float Rp = R[r * 3] * pv[0] + R[r * 3 + 1] * pv[1] + R[r * 3 + 2] * pv[2];
            c[r * 3 + 0] = R[r * 3 + 0] - (r == 0 ? 1.f : 0.f);
            c[r * 3 + 1] = R[r * 3 + 1] - (r == 1 ? 1.f : 0.f);
            c[r * 3 + 2] = R[r * 3 + 2] - (r == 2 ? 1.f : 0.f);
            c[9 + r]     = pv[r] + t[r] - Rp;
        }
    }
    // g_coef visible to apply_k: griddepcontrol.wait orders on full kernel completion
}

// ---------------------------------------------------------------------------
// Pass 2 (secondary, PDL): prefetch 7 x 16B mask slices + axes BEFORE the
// dependency wait; read coefficients after. motion[b,c,v] =
// sum_{k<7} mask[b,k,v] * (M_bk[c,:].g_v + d_bk[c]).
// ---------------------------------------------------------------------------
__global__ void __launch_bounds__(APPLY_THREADS, 6)
apply_k(const float* __restrict__ mask, const float* __restrict__ grids,
        float* __restrict__ out)
{
    const int blocksPerB = NQ / APPLY_THREADS;   // 256
    const int b   = blockIdx.x / blocksPerB;
    const int blk = blockIdx.x % blocksPerB;
    const int tid = threadIdx.x;

    __shared__ __align__(16) float4 sbuf[7 * 256];   // 28 KB: 7 mask slices
    __shared__ float cf[84];
    __shared__ float ay[64], az[64];

    const int idx4 = blk * APPLY_THREADS + tid;
    const float4* mb = (const float4*)mask + ((size_t)b * 8) * NQ + idx4;

    // ---- prefetch: independent of primary's results ----
#pragma unroll
    for (int k = 0; k < 7; ++k)
        cp_async16(smem_u32(&sbuf[k * 256 + tid]), &mb[(size_t)k * NQ]);
    asm volatile("cp.async.commit_group;" ::: "memory");

    if (tid < 64) {
        ay[tid] = grids[NVOX + (tid << 6)];
        az[tid] = grids[2 * NVOX + tid];
    }
    const float gx = grids[(size_t)(blk >> 2) << 12];   // block-constant x-plane

    pdl_wait();                                      // primary grid fully done

    if (tid < 84) cf[tid] = g_coef[b * 84 + tid];    // coefficients now final
    __syncthreads();                                 // cf + axes ready

    asm volatile("cp.async.wait_group 0;" ::: "memory");  // own 16B slots ready

    const int v  = idx4 << 2;
    const int j  = (v >> 6) & 63;
    const int kk = v & 63;
    const float gy = ay[j];
    const float gz[4] = { az[kk], az[kk + 1], az[kk + 2], az[kk + 3] };

    float mot[3][4] = {};
#pragma unroll
    for (int k = 0; k < 7; ++k) {
        const float4 m = sbuf[k * 256 + tid];
        const float mvv[4] = { m.x, m.y, m.z, m.w };
        const float* c = cf + k * 12;
#pragma unroll
        for (int cc = 0; cc < 3; ++cc) {
            const float m2   = c[cc * 3 + 2];
            const float base = fmaf(c[cc * 3], gx, fmaf(c[cc * 3 + 1], gy, c[9 + cc]));
#pragma unroll
            for (int t = 0; t < 4; ++t)
                mot[cc][t] = fmaf(mvv[t], fmaf(m2, gz[t], base), mot[cc][t]);
        }
    }

    float4* o4 = (float4*)out;
#pragma unroll
    for (int cc = 0; cc < 3; ++cc) {
        float4 o = { mot[cc][0], mot[cc][1], mot[cc][2], mot[cc][3] };
        o4[((size_t)b * 3 + cc) * NQ + idx4] = o;
    }
}

// ---------------------------------------------------------------------------
extern "C" void kernel_launch(void* const* d_in, const int* in_sizes, int n_in,
                              void* d_out, int out_size)
{
    const float* mask = nullptr;
    const float* tv   = nullptr;
    const float* rm   = nullptr;
    const float* gr   = nullptr;
    for (int i = 0; i < n_in; ++i) {
        switch (in_sizes[i]) {
            case 8388608: mask = (const float*)d_in[i]; break;   // (4,8,64,64,64)
            case 84:      tv   = (const float*)d_in[i]; break;   // (4,7,3)
            case 252:     rm   = (const float*)d_in[i]; break;   // (4,7,3,3)
            case 786432:  gr   = (const float*)d_in[i]; break;   // (3,64,64,64)
        }
    }

    // Primary
    reduce_k<<<NBLOCKS, RED_THREADS>>>(mask, gr, tv, rm);

    // Secondary with Programmatic Dependent Launch: may begin executing its
    // prefetch while reduce_k drains; griddepcontrol.wait guards the coef read.
    cudaLaunchConfig_t cfg = {};
    cfg.gridDim  = dim3(4 * (NQ / APPLY_THREADS), 1, 1);
    cfg.blockDim = dim3(APPLY_THREADS, 1, 1);
    cfg.dynamicSmemBytes = 0;
    cfg.stream = 0;                                  // legacy default stream (captured)
    cudaLaunchAttribute attr[1];
    attr[0].id = cudaLaunchAttributeProgrammaticStreamSerialization;
    attr[0].val.programmaticStreamSerializationAllowed = 1;
    cfg.attrs = attr;
    cfg.numAttrs = 1;
    cudaLaunchKernelEx(&cfg, apply_k, mask, gr, (float*)d_out);
}